// round 6
// baseline (speedup 1.0000x reference)
#include <cuda_runtime.h>
#include <cuda_bf16.h>
#include <math.h>
#include <stdint.h>

typedef __nv_bfloat16 BF;
#define T_ 512
#define B_ 64
#define H_ 1024
#define IN0 1536
#define OUTD 512
#define SLOT (B_*H_)
#define SLAB ((size_t)514*SLOT)
#define NBLK 128

__device__ __align__(16) BF gG0h[(size_t)NBLK*32*2560];
__device__ __align__(16) BF gG0l[(size_t)NBLK*32*2560];
__device__ __align__(16) BF gG1h[(size_t)NBLK*32*2048];
__device__ __align__(16) BF gG1l[(size_t)NBLK*32*2048];
__device__ __align__(16) BF gSkh[(size_t)2*NBLK*8*1024];
__device__ __align__(16) BF gSkl[(size_t)2*NBLK*8*1024];
__device__ __align__(16) BF gWoh[OUTD*H_];
__device__ __align__(16) BF gWol[OUTD*H_];
__device__ __align__(16) BF gXh[(size_t)T_*B_*IN0];
__device__ __align__(16) BF gXl[(size_t)T_*B_*IN0];
__device__ __align__(16) BF gHh[2*SLAB];
__device__ __align__(16) BF gHl[2*SLAB];

__device__ volatile unsigned gBarGen;
__device__ unsigned gBarCnt;

__device__ __forceinline__ float sigf(float x){ return 1.f/(1.f+expf(-x)); }
__device__ __forceinline__ void splitf(float v, BF* h, BF* l){
  BF a=__float2bfloat16(v); *h=a; *l=__float2bfloat16(v-__bfloat162float(a));
}
__device__ __forceinline__ void cp16(BF* d, const BF* s){
  unsigned u=(unsigned)__cvta_generic_to_shared(d);
  asm volatile("cp.async.cg.shared.global [%0],[%1],16;"::"r"(u),"l"(s));
}
__device__ __forceinline__ void cpc(){ asm volatile("cp.async.commit_group;"); }
template<int N> __device__ __forceinline__ void cpw(){ asm volatile("cp.async.wait_group %0;"::"n"(N)); }

__device__ __forceinline__ void gridbar(){
  __syncthreads();
  if(threadIdx.x==0){
    unsigned old = gBarGen;
    __threadfence();
    unsigned prev = atomicAdd(&gBarCnt,1u);
    if(prev==NBLK-1u){ gBarCnt=0u; __threadfence(); gBarGen=old+1u; }
    else { while(gBarGen==old){} }
    __threadfence();
  }
  __syncthreads();
}

// tiles: rows x 64 bf16, 128B rows, 8-way 16B XOR swizzle
__device__ __forceinline__ const BF* swp(const BF* t_, int r, int cseg){
  return t_ + r*64 + ((cseg ^ (r&7))<<3);
}
__device__ __forceinline__ void stT(BF* dh, BF* dl, const BF* ph, const BF* pl,
                                    int ld, int rows, int tid, int nthr){
  for(int u=tid; u<rows*8; u+=nthr){
    int r=u>>3, cs=u&7;
    int off = r*64 + ((cs ^ (r&7))<<3);
    size_t g=(size_t)r*ld + cs*8;
    cp16(dh+off, ph+g); cp16(dl+off, pl+g);
  }
}
__device__ __forceinline__ void ldsm4(unsigned a[4], const BF* p){
  unsigned u=(unsigned)__cvta_generic_to_shared(p);
  asm volatile("ldmatrix.sync.aligned.m8n8.x4.shared.b16 {%0,%1,%2,%3},[%4];"
    :"=r"(a[0]),"=r"(a[1]),"=r"(a[2]),"=r"(a[3]):"r"(u));
}
__device__ __forceinline__ void ldsm2(unsigned b[2], const BF* p){
  unsigned u=(unsigned)__cvta_generic_to_shared(p);
  asm volatile("ldmatrix.sync.aligned.m8n8.x2.shared.b16 {%0,%1},[%2];"
    :"=r"(b[0]),"=r"(b[1]):"r"(u));
}
__device__ __forceinline__ void mma(float c[4], const unsigned a[4], const unsigned b[2]){
  asm volatile("mma.sync.aligned.m16n8k16.row.col.f32.bf16.bf16.f32 "
    "{%0,%1,%2,%3},{%4,%5,%6,%7},{%8,%9},{%0,%1,%2,%3};"
    :"+f"(c[0]),"+f"(c[1]),"+f"(c[2]),"+f"(c[3])
    :"r"(a[0]),"r"(a[1]),"r"(a[2]),"r"(a[3]),"r"(b[0]),"r"(b[1]));
}
// one 32-wide K slice of C(16 x NT*8); A tile 64x64, W tile rows x 64
template<int NT>
__device__ __forceinline__ void mm32(float (*acc)[4], const BF* Ah,const BF* Al,
     const BF* Wh,const BF* Wl, int kbase, int rA,int cA,int nB,int cB){
#pragma unroll
  for(int kk=0;kk<2;kk++){
    int cs=(kbase>>3)+kk*2;
    unsigned ah[4],al[4];
    ldsm4(ah,swp(Ah,rA,cs+cA)); ldsm4(al,swp(Al,rA,cs+cA));
#pragma unroll
    for(int nt=0;nt<NT;nt++){
      unsigned bh[2],bl[2];
      ldsm2(bh,swp(Wh,nt*8+nB,cs+cB)); ldsm2(bl,swp(Wl,nt*8+nB,cs+cB));
      mma(acc[nt],ah,bh); mma(acc[nt],ah,bl); mma(acc[nt],al,bh);
    }
  }
}

// ---------------- prep ----------------
__global__ void k_prepX(const float* __restrict__ x){
  size_t n=(size_t)T_*B_*IN0;
  for(size_t i=(size_t)blockIdx.x*blockDim.x+threadIdx.x;i<n;i+=(size_t)gridDim.x*blockDim.x)
    splitf(x[i],&gXh[i],&gXl[i]);
}
__global__ void k_prepG(const float* __restrict__ Wih,const float* __restrict__ Whh,int layer){
  const int KA1=layer?H_:IN0, KG=KA1+H_;
  BF* dh=layer?gG1h:gG0h; BF* dl=layer?gG1l:gG0l;
  size_t n=(size_t)NBLK*32*KG;
  for(size_t i=(size_t)blockIdx.x*blockDim.x+threadIdx.x;i<n;i+=(size_t)gridDim.x*blockDim.x){
    int k=(int)(i%KG); int q=(int)(i/KG); int nr=q&31, blk=q>>5;
    int row=(nr>>3)*H_+blk*8+(nr&7);
    float v = (k<KA1)? Wih[(size_t)row*KA1+k] : Whh[(size_t)row*H_+(k-KA1)];
    splitf(v,&dh[i],&dl[i]);
  }
}
__global__ void k_prepS2(const float* __restrict__ Wh2,int layer){
  BF* dh=gSkh+(size_t)layer*NBLK*8*1024; BF* dl=gSkl+(size_t)layer*NBLK*8*1024;
  int n=NBLK*8*1024;
  for(int i=blockIdx.x*blockDim.x+threadIdx.x;i<n;i+=gridDim.x*blockDim.x){
    int k=i&1023; int q=i>>10; int nr=q&7, blk=q>>3;
    splitf(Wh2[(size_t)k*H_+blk*8+nr],&dh[i],&dl[i]);
  }
}
__global__ void k_prepWo(const float* __restrict__ W){
  for(int i=blockIdx.x*blockDim.x+threadIdx.x;i<OUTD*H_;i+=gridDim.x*blockDim.x)
    splitf(W[i],&gWoh[i],&gWol[i]);
}

// ---------------- persistent recurrence ----------------
__global__ void __launch_bounds__(256,1) k_persist(const int* __restrict__ mask,
    const float* __restrict__ h0, const float* __restrict__ c0,
    const float* __restrict__ bih0,const float* __restrict__ bhh0,const float* __restrict__ bh20,
    const float* __restrict__ bih1,const float* __restrict__ bhh1,const float* __restrict__ bh21)
{
  extern __shared__ char smx[];
  BF* sA=(BF*)smx;                         // 4 stages x (hi4096|lo4096)
  BF* sW=(BF*)(smx+65536);                 // 4 stages x (hi2048|lo2048)
  float* Cred=(float*)(smx+98304);         // 64 x 40
  const int tid=threadIdx.x, lane=tid&31, w=tid>>5, blk=blockIdx.x;
  const int kg=w>>2, r0=(w&3)*16;
  const int rA=r0+(lane&7)+((lane>>3)&1)*8, cA=(lane>>4)&1;
  const int nB=lane&7, cB=(lane>>3)&1;
  const int rr=r0+(lane>>2), cc=(lane&3)*2;
  const int kbase=kg*32;

  float creg[2][4];
  if(w<4){
#pragma unroll
    for(int q=0;q<2;q++)
#pragma unroll
      for(int p=0;p<2;p++){
        int r=rr+q*8, j=blk*8+cc+p, idx=q*2+p;
        creg[0][idx]=c0[(size_t)r*H_+j];
        creg[1][idx]=c0[(size_t)(B_+r)*H_+j];
#pragma unroll
        for(int L=0;L<2;L++){
          size_t b0=(size_t)L*SLAB+(size_t)r*H_+j;
          gHh[b0]=__float2bfloat16(0.f); gHl[b0]=__float2bfloat16(0.f);
          splitf(h0[(size_t)(L*B_+r)*H_+j],&gHh[b0+SLOT],&gHl[b0+SLOT]);
        }
      }
  }
  gridbar();

  for(int t=0;t<T_;t++){
#pragma unroll 1
    for(int L=0;L<2;L++){
      const int KA1=L?H_:IN0, KG=KA1+H_;
      const int NG=KG>>6, NIT=NG+16;
      const BF* Gh=(L?gG1h:gG0h)+(size_t)blk*32*KG;
      const BF* Gl=(L?gG1l:gG0l)+(size_t)blk*32*KG;
      const BF* Sh=gSkh+(size_t)L*NBLK*8*1024+(size_t)blk*8*1024;
      const BF* Sl=gSkl+(size_t)L*NBLK*8*1024+(size_t)blk*8*1024;
      const BF* skAh=gHh+(size_t)L*SLAB+(size_t)t*SLOT;
      const BF* skAl=gHl+(size_t)L*SLAB+(size_t)t*SLOT;

      float acc[5][4];
#pragma unroll
      for(int i=0;i<5;i++){acc[i][0]=0;acc[i][1]=0;acc[i][2]=0;acc[i][3]=0;}

      // stage lambda-equivalent
      auto do_stage=[&](int it){
        int st=it&3;
        BF* dA=sA+st*8192; BF* dW=sW+st*4096;
        if(it<NG){
          int k0=it*64;
          const BF *ph,*pl; int ld;
          if(L==0){
            if(k0<IN0){ph=gXh+(size_t)t*B_*IN0+k0; pl=gXl+(size_t)t*B_*IN0+k0; ld=IN0;}
            else {ph=gHh+(size_t)(t+1)*SLOT+(k0-IN0); pl=gHl+(size_t)(t+1)*SLOT+(k0-IN0); ld=H_;}
          }else{
            if(k0<H_){ph=gHh+(size_t)(t+2)*SLOT+k0; pl=gHl+(size_t)(t+2)*SLOT+k0; ld=H_;}
            else {ph=gHh+SLAB+(size_t)(t+1)*SLOT+(k0-H_); pl=gHl+SLAB+(size_t)(t+1)*SLOT+(k0-H_); ld=H_;}
          }
          stT(dA,dA+4096,ph,pl,ld,64,tid,256);
          stT(dW,dW+2048,Gh+k0,Gl+k0,KG,32,tid,256);
        }else{
          int k0=(it-NG)*64;
          stT(dA,dA+4096,skAh+k0,skAl+k0,H_,64,tid,256);
          stT(dW,dW+2048,Sh+k0,Sl+k0,1024,8,tid,256);
        }
        cpc();
      };

      do_stage(0); do_stage(1); do_stage(2);
#pragma unroll 1
      for(int it=0;it<NIT;it++){
        int rem=NIT-1-it;
        if(rem>1) cpw<2>(); else if(rem==1) cpw<1>(); else cpw<0>();
        __syncthreads();
        int st=it&3;
        BF* bA=sA+st*8192; BF* bW=sW+st*4096;
        if(it<NG) mm32<4>(acc,bA,bA+4096,bW,bW+2048,kbase,rA,cA,nB,cB);
        else      mm32<1>(acc+4,bA,bA+4096,bW,bW+2048,kbase,rA,cA,nB,cB);
        if(it+3<NIT) do_stage(it+3);
      }

      // k-split reduction
      if(w>=4){
#pragma unroll
        for(int nt=0;nt<5;nt++)
#pragma unroll
          for(int q=0;q<2;q++)
#pragma unroll
            for(int p=0;p<2;p++)
              Cred[(rr+q*8)*40+nt*8+cc+p]=acc[nt][q*2+p];
      }
      __syncthreads();
      if(w<4){
        const float* bi=L?bih1:bih0; const float* bh=L?bhh1:bhh0; const float* b2=L?bh21:bh20;
#pragma unroll
        for(int q=0;q<2;q++)
#pragma unroll
          for(int p=0;p<2;p++){
            int r=rr+q*8, jl=cc+p, j=blk*8+jl, idx=q*2+p;
            float ig=acc[0][idx]+Cred[r*40+jl]      +bi[j]     +bh[j];
            float fg=acc[1][idx]+Cred[r*40+8+jl]    +bi[H_+j]  +bh[H_+j];
            float gg=acc[2][idx]+Cred[r*40+16+jl]   +bi[2*H_+j]+bh[2*H_+j];
            float og=acc[3][idx]+Cred[r*40+24+jl]   +bi[3*H_+j]+bh[3*H_+j];
            float sk=acc[4][idx]+Cred[r*40+32+jl]   +b2[j];
            float cv=creg[L][idx];
            float cn=sigf(fg)*cv+sigf(ig)*tanhf(gg);
            float h1=sigf(og)*tanhf(cn);
            float h2=sigf(sk);
            int code=mask[(size_t)t*2*H_+(size_t)L*H_+j];
            float hn=(code!=1?h1:0.f)+(code!=0?h2:0.f);
            creg[L][idx]=cn;
            size_t hi=(size_t)L*SLAB+(size_t)(t+2)*SLOT+(size_t)r*H_+j;
            splitf(hn,&gHh[hi],&gHl[hi]);
          }
      }
      gridbar();
    }
  }
}

// ---------------- output GEMM ----------------
__global__ void __launch_bounds__(256,1) k_out(const float* __restrict__ bo, float* __restrict__ out){
  extern __shared__ char smx[];
  BF* sA=(BF*)smx;                 // 4 x (hi4096|lo4096)
  BF* sW=(BF*)(smx+65536);         // 4 x (hi4096|lo4096)
  float* Cred=(float*)(smx+131072);// 64x64
  const int tid=threadIdx.x, lane=tid&31, w=tid>>5;
  const int kg=w>>2, r0=(w&3)*16;
  const int rA=r0+(lane&7)+((lane>>3)&1)*8, cA=(lane>>4)&1;
  const int nB=lane&7, cB=(lane>>3)&1;
  const int rr=r0+(lane>>2), cc=(lane&3)*2;
  const int kbase=kg*32;
  const int t=blockIdx.x, n0=blockIdx.y*64;
  const BF* Ah=gHh+SLAB+(size_t)(t+2)*SLOT;
  const BF* Al=gHl+SLAB+(size_t)(t+2)*SLOT;
  const BF* Wh=gWoh+(size_t)n0*H_;
  const BF* Wl=gWol+(size_t)n0*H_;
  float acc[8][4];
#pragma unroll
  for(int i=0;i<8;i++){acc[i][0]=0;acc[i][1]=0;acc[i][2]=0;acc[i][3]=0;}
  auto do_stage=[&](int it){
    int st=it&3, k0=it*64;
    BF* dA=sA+st*8192; BF* dW=sW+st*8192;
    stT(dA,dA+4096,Ah+k0,Al+k0,H_,64,tid,256);
    stT(dW,dW+4096,Wh+k0,Wl+k0,H_,64,tid,256);
    cpc();
  };
  do_stage(0); do_stage(1); do_stage(2);
#pragma unroll 1
  for(int it=0;it<16;it++){
    int rem=15-it;
    if(rem>1) cpw<2>(); else if(rem==1) cpw<1>(); else cpw<0>();
    __syncthreads();
    int st=it&3;
    BF* bA=sA+st*8192; BF* bW=sW+st*8192;
    mm32<8>(acc,bA,bA+4096,bW,bW+4096,kbase,rA,cA,nB,cB);
    if(it+3<16) do_stage(it+3);
  }
  if(w>=4){
#pragma unroll
    for(int nt=0;nt<8;nt++)
#pragma unroll
      for(int q=0;q<2;q++)
#pragma unroll
        for(int p=0;p<2;p++)
          Cred[(rr+q*8)*64+nt*8+cc+p]=acc[nt][q*2+p];
  }
  __syncthreads();
  if(w<4){
#pragma unroll
    for(int nt=0;nt<8;nt++)
#pragma unroll
      for(int q=0;q<2;q++)
#pragma unroll
        for(int p=0;p<2;p++){
          int r=rr+q*8, col=n0+nt*8+cc+p;
          float v=acc[nt][q*2+p]+Cred[r*64+nt*8+cc+p]+bo[col];
          out[(size_t)t*B_*OUTD+(size_t)r*OUTD+col]=v;
        }
  }
}

extern "C" void kernel_launch(void* const* d_in, const int* in_sizes, int n_in,
                              void* d_out, int out_size) {
  const float* targets=(const float*)d_in[0];
  const float* h0  =(const float*)d_in[1];
  const float* c0  =(const float*)d_in[2];
  const int*   mask=(const int*)  d_in[3];
  const float* Wih0=(const float*)d_in[4];
  const float* Whh0=(const float*)d_in[5];
  const float* bih0=(const float*)d_in[6];
  const float* bhh0=(const float*)d_in[7];
  const float* Wih1=(const float*)d_in[8];
  const float* Whh1=(const float*)d_in[9];
  const float* bih1=(const float*)d_in[10];
  const float* bhh1=(const float*)d_in[11];
  const float* Wh20=(const float*)d_in[12];
  const float* bh20=(const float*)d_in[13];
  const float* Wh21=(const float*)d_in[14];
  const float* bh21=(const float*)d_in[15];
  const float* Wout=(const float*)d_in[16];
  const float* bout=(const float*)d_in[17];

  static int inited=0;
  if(!inited){
    cudaFuncSetAttribute(k_persist, cudaFuncAttributeMaxDynamicSharedMemorySize, 108544);
    cudaFuncSetAttribute(k_out,     cudaFuncAttributeMaxDynamicSharedMemorySize, 147456);
    inited=1;
  }
  k_prepX<<<4096,256>>>(targets);
  k_prepG<<<4096,256>>>(Wih0,Whh0,0);
  k_prepG<<<4096,256>>>(Wih1,Whh1,1);
  k_prepS2<<<512,256>>>(Wh20,0);
  k_prepS2<<<512,256>>>(Wh21,1);
  k_prepWo<<<512,256>>>(Wout);
  k_persist<<<NBLK,256,108544>>>(mask,h0,c0,bih0,bhh0,bh20,bih1,bhh1,bh21);
  k_out<<<dim3(T_,8),256,147456>>>(bout,(float*)d_out);
}